// round 2
// baseline (speedup 1.0000x reference)
#include <cuda_runtime.h>
#include <cuda_bf16.h>

// Problem constants: B=32, C=3, H=W=512
#define Bv 32
#define Cv 3
#define Hv 512
#define Wv 512
#define PLANE (Hv*Wv)            // 262144
#define NPLANES (Bv*Cv)          // 96
#define K1_BLOCKS_PER_PLANE 32   // 32 blocks x 256 thr x 32 elems = 262144

// Deterministic partial sums (no atomics): one slot per (plane, block)
__device__ float d_partial[NPLANES * K1_BLOCKS_PER_PLANE];
__device__ float d_sums[NPLANES];

__device__ __forceinline__ float fast_pow(float x, float g) {
    // x in [0,1): exp2(g*log2(x)); x==0 -> -inf -> exp2 -> 0 (correct)
    return __powf(x, g);
}

// ---------------- Kernel 1: per-plane sum of x^gamma ----------------
__global__ void __launch_bounds__(256) k1_pow_sum(const float* __restrict__ x,
                                                 const float* __restrict__ gamma) {
    const int plane = blockIdx.y;            // b*3 + c
    const int b = plane / Cv;
    const float g = __ldg(&gamma[b]);
    const float4* px = (const float4*)(x + (size_t)plane * PLANE);

    float s = 0.f;
    int base = blockIdx.x * 2048 + threadIdx.x;   // 2048 float4 per block
#pragma unroll
    for (int k = 0; k < 8; k++) {
        float4 v = px[base + k * 256];
        s += fast_pow(v.x, g);
        s += fast_pow(v.y, g);
        s += fast_pow(v.z, g);
        s += fast_pow(v.w, g);
    }
#pragma unroll
    for (int o = 16; o; o >>= 1) s += __shfl_xor_sync(0xFFFFFFFFu, s, o);

    __shared__ float ws[8];
    int lane = threadIdx.x & 31, w = threadIdx.x >> 5;
    if (lane == 0) ws[w] = s;
    __syncthreads();
    if (w == 0) {
        s = (lane < 8) ? ws[lane] : 0.f;
#pragma unroll
        for (int o = 4; o; o >>= 1) s += __shfl_xor_sync(0xFFFFFFFFu, s, o);
        if (lane == 0) d_partial[plane * K1_BLOCKS_PER_PLANE + blockIdx.x] = s;
    }
}

// ---------------- Kernel 1b: fold partials (deterministic) ----------------
__global__ void k1b_fold() {
    int p = threadIdx.x;
    if (p < NPLANES) {
        float s = 0.f;
#pragma unroll
        for (int i = 0; i < K1_BLOCKS_PER_PLANE; i++)
            s += d_partial[p * K1_BLOCKS_PER_PLANE + i];
        d_sums[p] = s;
    }
}

// ---------------- Kernel 2: recompute + contrast + sharpen blend ----------------
// 32x32 output tile, 1-px halo, block(32,8), each thread -> 4 consecutive rows
__global__ void __launch_bounds__(256) k2_main(const float* __restrict__ x,
                                               const float* __restrict__ gamma,
                                               const float* __restrict__ wb,
                                               const float* __restrict__ contrast,
                                               const float* __restrict__ sharpen,
                                               float* __restrict__ out) {
    const int plane = blockIdx.z;            // b*3 + c
    const int b = plane / Cv;
    const float g  = __ldg(&gamma[b]);
    const float w  = __ldg(&wb[plane]);      // wb[b][c] == wb[plane]
    const float ct = __ldg(&contrast[b]);
    const float s  = __ldg(&sharpen[b]);
    const float mean = d_sums[plane] * w * (1.0f / (float)PLANE);
    const float beta = mean - mean * ct;     // mean*(1-contrast)

    __shared__ float t[34][34];

    const float* __restrict__ px = x + (size_t)plane * PLANE;
    const int gx0 = blockIdx.x * 32 - 1;
    const int gy0 = blockIdx.y * 32 - 1;
    const int tid = threadIdx.y * 32 + threadIdx.x;

    // Load halo tile, apply pow/wb/contrast/clip into smem (zero pad OOB)
#pragma unroll
    for (int i = tid; i < 34 * 34; i += 256) {
        int r  = i / 34;
        int cc = i - r * 34;
        int gy = gy0 + r, gx = gx0 + cc;
        float tv = 0.f;
        if ((unsigned)gy < (unsigned)Hv && (unsigned)gx < (unsigned)Wv) {
            float v = px[gy * Wv + gx];
            float y = fast_pow(v, g) * w;
            tv = fminf(fmaxf(fmaf(y, ct, beta), 0.f), 1.f);
        }
        t[r][cc] = tv;
    }
    __syncthreads();

    const int tx = threadIdx.x;
    const int rbase = threadIdx.y * 4;       // 4 consecutive output rows per thread
    float* __restrict__ po = out + (size_t)plane * PLANE;

    // Row sums shared across the vertical window (6 rowsums serve 4 outputs)
    float rs[6];
#pragma unroll
    for (int j = 0; j < 6; j++)
        rs[j] = t[rbase + j][tx] + t[rbase + j][tx + 1] + t[rbase + j][tx + 2];

#pragma unroll
    for (int k = 0; k < 4; k++) {
        float ctr = t[rbase + k + 1][tx + 1];
        float s9  = rs[k] + rs[k + 1] + rs[k + 2];
        float sharp = fmaf(10.f, ctr, -s9);           // 9*c - 8 neighbors
        float o = fmaf(s, sharp - ctr, ctr);          // s*sharp + (1-s)*c
        o = fminf(fmaxf(o, 0.f), 1.f);
        int gy = blockIdx.y * 32 + rbase + k;
        int gx = blockIdx.x * 32 + tx;
        po[gy * Wv + gx] = o;
    }
}

extern "C" void kernel_launch(void* const* d_in, const int* in_sizes, int n_in,
                              void* d_out, int out_size) {
    const float* x        = (const float*)d_in[0];
    const float* gamma    = (const float*)d_in[1];
    const float* wb       = (const float*)d_in[2];
    const float* contrast = (const float*)d_in[3];
    const float* sharpen  = (const float*)d_in[4];
    float* out = (float*)d_out;

    dim3 g1(K1_BLOCKS_PER_PLANE, NPLANES);
    k1_pow_sum<<<g1, 256>>>(x, gamma);
    k1b_fold<<<1, 128>>>();
    dim3 g2(Wv / 32, Hv / 32, NPLANES);
    k2_main<<<g2, dim3(32, 8)>>>(x, gamma, wb, contrast, sharpen, out);
}

// round 3
// speedup vs baseline: 1.5459x; 1.5459x over previous
#include <cuda_runtime.h>
#include <cuda_bf16.h>

// Problem constants: B=32, C=3, H=W=512
#define Bv 32
#define Cv 3
#define Hv 512
#define Wv 512
#define PLANE (Hv*Wv)            // 262144
#define NPLANES (Bv*Cv)          // 96
#define K1_BLOCKS_PER_PLANE 32   // 32 blocks x 256 thr x 32 elems = 262144

// Deterministic partial sums (no atomics): one slot per (plane, block)
__device__ float d_partial[NPLANES * K1_BLOCKS_PER_PLANE];

__device__ __forceinline__ float fast_pow(float x, float g) {
    return __powf(x, g);     // MUFU.LG2 + FMUL + MUFU.EX2 ; 0^g -> 0 correct
}

// ---------------- Kernel 1: per-plane sum of x^gamma ----------------
__global__ void __launch_bounds__(256) k1_pow_sum(const float* __restrict__ x,
                                                 const float* __restrict__ gamma) {
    const int plane = blockIdx.y;            // b*3 + c
    const int b = plane / Cv;
    const float g = __ldg(&gamma[b]);
    const float4* px = (const float4*)(x + (size_t)plane * PLANE);

    float s0 = 0.f, s1 = 0.f, s2 = 0.f, s3 = 0.f;
    int base = blockIdx.x * 2048 + threadIdx.x;   // 2048 float4 per block
#pragma unroll
    for (int k = 0; k < 8; k++) {
        float4 v = px[base + k * 256];
        s0 += fast_pow(v.x, g);
        s1 += fast_pow(v.y, g);
        s2 += fast_pow(v.z, g);
        s3 += fast_pow(v.w, g);
    }
    float s = (s0 + s1) + (s2 + s3);
#pragma unroll
    for (int o = 16; o; o >>= 1) s += __shfl_xor_sync(0xFFFFFFFFu, s, o);

    __shared__ float ws[8];
    int lane = threadIdx.x & 31, w = threadIdx.x >> 5;
    if (lane == 0) ws[w] = s;
    __syncthreads();
    if (w == 0) {
        s = (lane < 8) ? ws[lane] : 0.f;
#pragma unroll
        for (int o = 4; o; o >>= 1) s += __shfl_xor_sync(0xFFFFFFFFu, s, o);
        if (lane == 0) d_partial[plane * K1_BLOCKS_PER_PLANE + blockIdx.x] = s;
    }
}

// ---------------- Kernel 2: recompute + contrast + sharpen blend ----------------
// Full-width strip: 512x8 outputs per block, 10 input rows in smem (rows padded
// to 514 floats; columns 0 and 513 are permanent zeros = conv zero-padding).
// Block: 256 threads.
#define SROW 514
__global__ void __launch_bounds__(256) k2_main(const float* __restrict__ x,
                                               const float* __restrict__ gamma,
                                               const float* __restrict__ wb,
                                               const float* __restrict__ contrast,
                                               const float* __restrict__ sharpen,
                                               float* __restrict__ out) {
    const int plane = blockIdx.y;            // b*3 + c
    const int b = plane / Cv;
    const float g  = __ldg(&gamma[b]);
    const float w  = __ldg(&wb[plane]);      // wb[b][c] flattens to wb[plane]
    const float ct = __ldg(&contrast[b]);
    const float s  = __ldg(&sharpen[b]);

    __shared__ float t[10][SROW];
    __shared__ float s_beta;

    const int tid = threadIdx.x;

    // Fold the 32 deterministic partials for this plane (thread 0), broadcast.
    if (tid == 0) {
        float acc = 0.f;
#pragma unroll
        for (int i = 0; i < K1_BLOCKS_PER_PLANE; i++)
            acc += d_partial[plane * K1_BLOCKS_PER_PLANE + i];
        float mean = acc * w * (1.0f / (float)PLANE);
        s_beta = mean - mean * ct;           // mean*(1-contrast)
    }
    // Zero the padding columns (20 slots)
    if (tid < 20) {
        int r = tid >> 1;
        t[r][(tid & 1) ? (SROW - 1) : 0] = 0.f;
    }
    __syncthreads();
    const float beta = s_beta;

    const float* __restrict__ px = x + (size_t)plane * PLANE;
    const int gy0 = blockIdx.x * 8 - 1;      // first input row of the strip

    // Load 10 rows x 128 float4, apply pow/wb/contrast/clip into smem.
    // 1280 float4 / 256 threads = 5 each. OOB rows (image top/bottom) -> zeros.
#pragma unroll
    for (int it = 0; it < 5; it++) {
        int i = tid + it * 256;
        int r = i >> 7;                      // 0..9
        int q = i & 127;                     // float4 index in row
        int gy = gy0 + r;
        float4 res = make_float4(0.f, 0.f, 0.f, 0.f);
        if ((unsigned)gy < (unsigned)Hv) {
            float4 v = ((const float4*)(px + gy * Wv))[q];
            res.x = fminf(fmaxf(fmaf(fast_pow(v.x, g) * w, ct, beta), 0.f), 1.f);
            res.y = fminf(fmaxf(fmaf(fast_pow(v.y, g) * w, ct, beta), 0.f), 1.f);
            res.z = fminf(fmaxf(fmaf(fast_pow(v.z, g) * w, ct, beta), 0.f), 1.f);
            res.w = fminf(fmaxf(fmaf(fast_pow(v.w, g) * w, ct, beta), 0.f), 1.f);
        }
        float* dst = &t[r][q * 4 + 1];
        dst[0] = res.x; dst[1] = res.y; dst[2] = res.z; dst[3] = res.w;
    }
    __syncthreads();

    // Compute: each thread -> 4 cols x 4 rows.
    const int colg = tid & 127;              // column group (4 cols)
    const int rh   = tid >> 7;               // 0..1 -> rows 0-3 / 4-7
    const int c0   = colg * 4;               // smem col base (shifted layout)
    const int rbase = rh * 4;                // smem row of first window top

    float rs[6][4];                          // sliding 3-col sums per row
    float ctr[4][4];                         // centers for output rows
#pragma unroll
    for (int j = 0; j < 6; j++) {
        const float* row = &t[rbase + j][c0];
        float f0 = row[0], f1 = row[1], f2 = row[2],
              f3 = row[3], f4 = row[4], f5 = row[5];
        rs[j][0] = f0 + f1 + f2;
        rs[j][1] = f1 + f2 + f3;
        rs[j][2] = f2 + f3 + f4;
        rs[j][3] = f3 + f4 + f5;
        if (j >= 1 && j <= 4) {
            ctr[j - 1][0] = f1; ctr[j - 1][1] = f2;
            ctr[j - 1][2] = f3; ctr[j - 1][3] = f4;
        }
    }

    float* __restrict__ po = out + (size_t)plane * PLANE;
#pragma unroll
    for (int k = 0; k < 4; k++) {
        float4 o4;
        float* o = (float*)&o4;
#pragma unroll
        for (int m = 0; m < 4; m++) {
            float c = ctr[k][m];
            float s9 = rs[k][m] + rs[k + 1][m] + rs[k + 2][m];
            float sharp = fmaf(10.f, c, -s9);          // 9c - 8 neighbors
            float v = fmaf(s, sharp - c, c);           // blend
            o[m] = fminf(fmaxf(v, 0.f), 1.f);
        }
        int gy = blockIdx.x * 8 + rbase + k;
        ((float4*)(po + gy * Wv))[colg] = o4;
    }
}

extern "C" void kernel_launch(void* const* d_in, const int* in_sizes, int n_in,
                              void* d_out, int out_size) {
    const float* x        = (const float*)d_in[0];
    const float* gamma    = (const float*)d_in[1];
    const float* wb       = (const float*)d_in[2];
    const float* contrast = (const float*)d_in[3];
    const float* sharpen  = (const float*)d_in[4];
    float* out = (float*)d_out;

    dim3 g1(K1_BLOCKS_PER_PLANE, NPLANES);
    k1_pow_sum<<<g1, 256>>>(x, gamma);
    dim3 g2(Hv / 8, NPLANES);               // 64 strips x 96 planes = 6144 blocks
    k2_main<<<g2, 256>>>(x, gamma, wb, contrast, sharpen, out);
}